// round 16
// baseline (speedup 1.0000x reference)
#include <cuda_runtime.h>
#include <cuda_bf16.h>
#include <mma.h>
#include <math.h>
#include <stdint.h>

using namespace nvcuda;

constexpr int N_    = 8192;
constexpr int IN_F_ = 512;
constexpr int D_    = 64;
constexpr float LRELU_A = 0.2f;

constexpr int RTF    = 128;           // rows per flash CTA
constexpr int TJ     = 64;            // j-tile (K per mma group)
constexpr int JSPLIT = 4;
constexpr int JSL    = N_ / JSPLIT;   // 2048
constexpr int NTILES = JSL / TJ;      // 32

// smem layout (bytes from dynamic base; bf16 rows padded to 72 elems = 144B)
constexpr int PHI = 0;                 // P hi  [128][72] bf16 = 18432
constexpr int PLO = 18432;             // P lo
constexpr int HHI = 36864;             // H^T hi [64][72] bf16 = 9216
constexpr int HLO = 46080;             // H^T lo
constexpr int RAO = 55296;             // rowA float4[128] = 2048
constexpr int SSO = 57344;             // row sums float[128]
constexpr int SMEM_DYN = 57856;

// ---- device scratch ----
__device__ __align__(16) float  g_h[N_ * D_];
__device__ __align__(16) float4 g_rowA[N_];              // (EA, EA2, thr, al)
__device__ __align__(16) float2 g_EBP[N_];               // (EB, EB2)
__device__ __align__(16) __nv_bfloat16 g_hThi[D_ * N_];  // H^T hi  [n][j]
__device__ __align__(16) __nv_bfloat16 g_hTlo[D_ * N_];  // H^T lo
__device__ __align__(16) float  g_pacc[JSPLIT][N_][D_];
__device__ float g_psum[JSPLIT][N_];

__device__ __forceinline__ uint32_t cvt_bf16x2(float lo, float hi) {
    uint32_t r;
    asm("cvt.rn.bf16x2.f32 %0, %2, %1;" : "=r"(r) : "f"(lo), "f"(hi));
    return r;
}

// ---------------------------------------------------------------------------
// Phase 1: h = input @ W   (unchanged, passing since R8)
// ---------------------------------------------------------------------------
constexpr int BM = 32;
constexpr int BK = 32;

__global__ void __launch_bounds__(256) k_gemm(const float* __restrict__ inp,
                                              const float* __restrict__ W) {
    __shared__ float As[BK][BM + 1];
    __shared__ float Bs[BK][D_];
    const int tid  = threadIdx.x;
    const int row0 = blockIdx.x * BM;
    const int ty   = tid >> 4;
    const int tx   = tid & 15;

    float acc[2][4];
#pragma unroll
    for (int i = 0; i < 2; ++i)
#pragma unroll
        for (int j = 0; j < 4; ++j) acc[i][j] = 0.0f;

    for (int k0 = 0; k0 < IN_F_; k0 += BK) {
        __syncthreads();
        {
            const int r = tid >> 3;
            const int c = (tid & 7) * 4;
            float4 v = *(const float4*)(inp + (size_t)(row0 + r) * IN_F_ + k0 + c);
            As[c + 0][r] = v.x; As[c + 1][r] = v.y;
            As[c + 2][r] = v.z; As[c + 3][r] = v.w;
        }
        {
            const int kk = tid >> 3;
            const int c  = (tid & 7) * 8;
            float4 v0 = *(const float4*)(W + (size_t)(k0 + kk) * D_ + c);
            float4 v1 = *(const float4*)(W + (size_t)(k0 + kk) * D_ + c + 4);
            *(float4*)&Bs[kk][c]     = v0;
            *(float4*)&Bs[kk][c + 4] = v1;
        }
        __syncthreads();
#pragma unroll
        for (int kk = 0; kk < BK; ++kk) {
            float a0 = As[kk][ty * 2], a1 = As[kk][ty * 2 + 1];
            float4 b4 = *(const float4*)&Bs[kk][tx * 4];
            acc[0][0] += a0 * b4.x; acc[0][1] += a0 * b4.y;
            acc[0][2] += a0 * b4.z; acc[0][3] += a0 * b4.w;
            acc[1][0] += a1 * b4.x; acc[1][1] += a1 * b4.y;
            acc[1][2] += a1 * b4.z; acc[1][3] += a1 * b4.w;
        }
    }
#pragma unroll
    for (int i = 0; i < 2; ++i) {
        float4 v = make_float4(acc[i][0], acc[i][1], acc[i][2], acc[i][3]);
        *(float4*)(g_h + (size_t)(row0 + ty * 2 + i) * D_ + tx * 4) = v;
    }
}

// ---------------------------------------------------------------------------
// Phase 1b: per-node attention scalars + exponentials.
// ---------------------------------------------------------------------------
__global__ void __launch_bounds__(256) k_att(const float* __restrict__ a) {
    const int warp = threadIdx.x >> 5;
    const int lane = threadIdx.x & 31;
    const int row  = blockIdx.x * 8 + warp;
    const float* hr = g_h + (size_t)row * D_;
    float h0 = hr[lane], h1 = hr[lane + 32];
    float sl = h0 * a[lane]      + h1 * a[lane + 32];
    float sr = h0 * a[64 + lane] + h1 * a[96 + lane];
#pragma unroll
    for (int o = 16; o >= 1; o >>= 1) {
        sl += __shfl_xor_sync(0xffffffffu, sl, o);
        sr += __shfl_xor_sync(0xffffffffu, sr, o);
    }
    if (lane == 0) {
        g_rowA[row] = make_float4(expf(sl), expf(LRELU_A * sl), expf(-sl), sl);
        g_EBP[row]  = make_float2(expf(sr), expf(LRELU_A * sr));
    }
}

// ---------------------------------------------------------------------------
// Phase 1c: H^T hi/lo bf16 split  (g_hThi/lo[n][j] = split of g_h[j][n])
// ---------------------------------------------------------------------------
__global__ void __launch_bounds__(256) k_hT() {
    __shared__ float ts[64][65];
    const int j0  = blockIdx.x * 64;
    const int tid = threadIdx.x;
#pragma unroll
    for (int i = 0; i < 4; ++i) {
        int idx = tid + i * 256;
        int r = idx >> 4, c4 = (idx & 15) * 4;
        float4 v = *(const float4*)(g_h + (size_t)(j0 + r) * D_ + c4);
        ts[r][c4] = v.x; ts[r][c4 + 1] = v.y; ts[r][c4 + 2] = v.z; ts[r][c4 + 3] = v.w;
    }
    __syncthreads();
#pragma unroll
    for (int i = 0; i < 16; ++i) {
        int idx = tid + i * 256;
        int n = idx >> 6, jl = idx & 63;
        float h = ts[jl][n];
        __nv_bfloat16 hi = __float2bfloat16(h);
        float lo = h - __bfloat162float(hi);
        g_hThi[(size_t)n * N_ + j0 + jl] = hi;
        g_hTlo[(size_t)n * N_ + j0 + jl] = __float2bfloat16(lo);
    }
}

// ---------------------------------------------------------------------------
// Phase 2: WMMA bf16 flash.  D(128x64 f32) += Phi*Hhi + Phi*Hlo + Plo*Hhi
//   adj for tile t+1 prefetched into registers during tile t's mma phase.
// ---------------------------------------------------------------------------
__global__ void __launch_bounds__(256, 2) k_flash(const int* __restrict__ adj) {
    extern __shared__ char sm[];
    __nv_bfloat16* Phi = (__nv_bfloat16*)(sm + PHI);
    __nv_bfloat16* Plo = (__nv_bfloat16*)(sm + PLO);
    __nv_bfloat16* Hhi = (__nv_bfloat16*)(sm + HHI);
    __nv_bfloat16* Hlo = (__nv_bfloat16*)(sm + HLO);
    float4* rA = (float4*)(sm + RAO);
    float*  ss = (float*)(sm + SSO);

    const int tid  = threadIdx.x;
    const int wid  = tid >> 5;
    const int lane = tid & 31;
    const int ib   = blockIdx.x & 63;
    const int sp   = blockIdx.x >> 6;
    const int i0   = ib * RTF;
    const int jb   = sp * JSL;

    if (tid < RTF) {
        rA[tid] = g_rowA[i0 + tid];
        ss[tid] = 0.0f;
    }

    wmma::fragment<wmma::accumulator, 16, 16, 16, float> acc[4];
#pragma unroll
    for (int n = 0; n < 4; ++n) wmma::fill_fragment(acc[n], 0.0f);

    const int sub = lane >> 3;     // row-within-warp-group
    const int l8  = lane & 7;      // j-chunk of 4
    const float4* ebp = (const float4*)(g_EBP + jb);

    // adj row pointers (int4 granularity) for this thread's 4 rows
    const int4* adjp[4];
#pragma unroll
    for (int it = 0; it < 4; ++it)
        adjp[it] = (const int4*)(adj + (size_t)(i0 + it * 32 + wid * 4 + sub) * N_ + jb);

    // prefetch adj for tile 0
    int4 av[8];
#pragma unroll
    for (int it = 0; it < 4; ++it)
#pragma unroll
        for (int q = 0; q < 2; ++q)
            av[it * 2 + q] = adjp[it][q * 8 + l8];

    for (int t = 0; t < NTILES; ++t) {
        const int jg = jb + t * TJ;
        __syncthreads();   // prev mma done with smem

        // ---- H^T tiles (hi+lo): 64 n x 64 k bf16 each ----
#pragma unroll
        for (int rep = 0; rep < 2; ++rep) {
            int idx = tid + rep * 256;       // 0..511
            int n = idx >> 3, u = idx & 7;   // 8 bf16 per chunk
            int4 vh = *(const int4*)(g_hThi + (size_t)n * N_ + jg + u * 8);
            int4 vl = *(const int4*)(g_hTlo + (size_t)n * N_ + jg + u * 8);
            *(int4*)((char*)Hhi + n * 144 + u * 16) = vh;
            *(int4*)((char*)Hlo + n * 144 + u * 16) = vl;
        }

        // ---- hoisted EB loads (depend on t,j only, not row) ----
        const float4 ea0 = ebp[t * 32 + l8 * 2];
        const float4 eb0 = ebp[t * 32 + l8 * 2 + 1];
        const float4 ea1 = ebp[t * 32 + 16 + l8 * 2];
        const float4 eb1 = ebp[t * 32 + 16 + l8 * 2 + 1];

        // ---- P tiles: warp covers 4 rows x 64 j per pass, 4 passes ----
#pragma unroll
        for (int it = 0; it < 4; ++it) {
            const int row = it * 32 + wid * 4 + sub;
            const float4 rv = rA[row];
            const float EA = rv.x, EA2 = rv.y, thr = rv.z;
            float rs = 0.0f;
#pragma unroll
            for (int q = 0; q < 2; ++q) {
                const int j = q * 32 + l8 * 4;
                const int4   m  = av[it * 2 + q];
                const float4 ea = q ? ea1 : ea0;
                const float4 eb = q ? eb1 : eb0;
                float p0 = (ea.x > thr) ? EA * ea.x : EA2 * ea.y;  p0 = m.x ? p0 : 0.0f;
                float p1 = (ea.z > thr) ? EA * ea.z : EA2 * ea.w;  p1 = m.y ? p1 : 0.0f;
                float p2 = (eb.x > thr) ? EA * eb.x : EA2 * eb.y;  p2 = m.z ? p2 : 0.0f;
                float p3 = (eb.z > thr) ? EA * eb.z : EA2 * eb.w;  p3 = m.w ? p3 : 0.0f;
                rs += p0 + p1 + p2 + p3;
                uint32_t h01 = cvt_bf16x2(p0, p1);
                uint32_t h23 = cvt_bf16x2(p2, p3);
                float l0 = p0 - __uint_as_float(h01 << 16);
                float l1 = p1 - __uint_as_float(h01 & 0xFFFF0000u);
                float l2 = p2 - __uint_as_float(h23 << 16);
                float l3 = p3 - __uint_as_float(h23 & 0xFFFF0000u);
                uint32_t q01 = cvt_bf16x2(l0, l1);
                uint32_t q23 = cvt_bf16x2(l2, l3);
                *(uint2*)((char*)Phi + row * 144 + j * 2) = make_uint2(h01, h23);
                *(uint2*)((char*)Plo + row * 144 + j * 2) = make_uint2(q01, q23);
            }
#pragma unroll
            for (int o = 4; o >= 1; o >>= 1)
                rs += __shfl_xor_sync(0xffffffffu, rs, o);
            if (l8 == 0) ss[row] += rs;
        }

        // ---- prefetch adj(t+1): LDGs fly across the barrier + mma phase ----
        if (t + 1 < NTILES) {
#pragma unroll
            for (int it = 0; it < 4; ++it)
#pragma unroll
                for (int q = 0; q < 2; ++q)
                    av[it * 2 + q] = adjp[it][(t + 1) * 16 + q * 8 + l8];
        }
        __syncthreads();   // P/H tiles visible

        // ---- mma phase: warp owns rows wid*16..+15, all 64 cols ----
        const __nv_bfloat16* pw_hi = Phi + wid * 16 * 72;
        const __nv_bfloat16* pw_lo = Plo + wid * 16 * 72;
#pragma unroll
        for (int k = 0; k < 4; ++k) {
            wmma::fragment<wmma::matrix_a, 16, 16, 16, __nv_bfloat16, wmma::row_major> ahi, alo;
            wmma::load_matrix_sync(ahi, pw_hi + k * 16, 72);
            wmma::load_matrix_sync(alo, pw_lo + k * 16, 72);
#pragma unroll
            for (int n = 0; n < 4; ++n) {
                wmma::fragment<wmma::matrix_b, 16, 16, 16, __nv_bfloat16, wmma::col_major> bhi, blo;
                wmma::load_matrix_sync(bhi, Hhi + n * 16 * 72 + k * 16, 72);
                wmma::load_matrix_sync(blo, Hlo + n * 16 * 72 + k * 16, 72);
                wmma::mma_sync(acc[n], ahi, bhi, acc[n]);
                wmma::mma_sync(acc[n], ahi, blo, acc[n]);
                wmma::mma_sync(acc[n], alo, bhi, acc[n]);
            }
        }
    }
    __syncthreads();

    // ---- epilogue: partial sums to global ----
    if (tid < RTF) g_psum[sp][i0 + tid] = ss[tid];
#pragma unroll
    for (int n = 0; n < 4; ++n)
        wmma::store_matrix_sync(&g_pacc[sp][i0 + wid * 16][n * 16], acc[n], 64,
                                wmma::mem_row_major);
}

// ---------------------------------------------------------------------------
// Phase 3: combine partials, divide, ELU.
// ---------------------------------------------------------------------------
__global__ void __launch_bounds__(256) k_reduce(float* __restrict__ out) {
    const int idx = blockIdx.x * 256 + threadIdx.x;
    const int row = idx >> 4;
    const int c4  = (idx & 15) * 4;
    float4 s = make_float4(0.f, 0.f, 0.f, 0.f);
    float den = 0.0f;
#pragma unroll
    for (int sp = 0; sp < JSPLIT; ++sp) {
        float4 v = *(const float4*)&g_pacc[sp][row][c4];
        s.x += v.x; s.y += v.y; s.z += v.z; s.w += v.w;
        den += g_psum[sp][row];
    }
    float inv = 1.0f / den;
    float v0 = s.x * inv, v1 = s.y * inv, v2 = s.z * inv, v3 = s.w * inv;
    v0 = (v0 > 0.f) ? v0 : expm1f(v0);
    v1 = (v1 > 0.f) ? v1 : expm1f(v1);
    v2 = (v2 > 0.f) ? v2 : expm1f(v2);
    v3 = (v3 > 0.f) ? v3 : expm1f(v3);
    *(float4*)(out + (size_t)row * D_ + c4) = make_float4(v0, v1, v2, v3);
}

// ---------------------------------------------------------------------------
extern "C" void kernel_launch(void* const* d_in, const int* in_sizes, int n_in,
                              void* d_out, int out_size) {
    const float* inp = (const float*)d_in[0];   // (8192, 512) f32
    const int*   adj = (const int*)d_in[1];     // (8192, 8192) i32
    const float* W   = (const float*)d_in[2];   // (512, 64) f32
    const float* a   = (const float*)d_in[3];   // (128, 1) f32
    float* out = (float*)d_out;                 // (8192, 64) f32

    cudaFuncSetAttribute(k_flash, cudaFuncAttributeMaxDynamicSharedMemorySize, SMEM_DYN);

    k_gemm  <<<N_ / BM, 256>>>(inp, W);
    k_att   <<<N_ / 8,  256>>>(a);
    k_hT    <<<N_ / 64, 256>>>();
    k_flash <<<(N_ / RTF) * JSPLIT, 256, SMEM_DYN>>>(adj);
    k_reduce<<<N_ * 16 / 256, 256>>>(out);
}